// round 15
// baseline (speedup 1.0000x reference)
#include <cuda_runtime.h>
#include <cuda_bf16.h>
#include <math.h>

// ---------------- problem constants ----------------
#define NWIN 256
#define NTOK 256
#define NC   384
#define NH   12
#define DH   32
#define MROWS (NWIN*NTOK)
#define BHD (NTOK*DH)

typedef unsigned long long u64;
typedef unsigned int u32;

// ---------------- mma / ldmatrix helpers ------
__device__ __forceinline__ void mma16816(float c[4], const u32 a[4], u32 b0, u32 b1) {
    asm volatile(
        "mma.sync.aligned.m16n8k16.row.col.f32.bf16.bf16.f32 "
        "{%0,%1,%2,%3},{%4,%5,%6,%7},{%8,%9},{%0,%1,%2,%3};"
        : "+f"(c[0]), "+f"(c[1]), "+f"(c[2]), "+f"(c[3])
        : "r"(a[0]), "r"(a[1]), "r"(a[2]), "r"(a[3]), "r"(b0), "r"(b1));
}
__device__ __forceinline__ void ldmx4(u32 r[4], u32 addr) {
    asm volatile("ldmatrix.sync.aligned.m8n8.x4.shared.b16 {%0,%1,%2,%3}, [%4];"
        : "=r"(r[0]), "=r"(r[1]), "=r"(r[2]), "=r"(r[3]) : "r"(addr));
}
__device__ __forceinline__ u32 smem_to_u32(const void* p) {
    u32 a;
    asm("{ .reg .u64 t; cvta.to.shared.u64 t, %1; cvt.u32.u64 %0, t; }" : "=r"(a) : "l"(p));
    return a;
}
__device__ __forceinline__ void splitb(float x, __nv_bfloat16& hh, __nv_bfloat16& hl) {
    hh = __float2bfloat16(x);
    hl = __float2bfloat16(x - __bfloat162float(hh));
}
__device__ __forceinline__ u32 packb(__nv_bfloat16 a, __nv_bfloat16 b) {
    __nv_bfloat162 h(a, b);
    return *(u32*)&h;
}
// pack 8 fp32 -> 8 bf16 (hi parts)
__device__ __forceinline__ uint4 pack8h(float4 a, float4 b) {
    uint4 r;
    r.x = packb(__float2bfloat16(a.x), __float2bfloat16(a.y));
    r.y = packb(__float2bfloat16(a.z), __float2bfloat16(a.w));
    r.z = packb(__float2bfloat16(b.x), __float2bfloat16(b.y));
    r.w = packb(__float2bfloat16(b.z), __float2bfloat16(b.w));
    return r;
}
// pack 8 fp32 -> 8 bf16 (lo parts), identical math to split_kernel
__device__ __forceinline__ uint4 pack8l(float4 a, float4 b) {
    float v[8] = {a.x,a.y,a.z,a.w,b.x,b.y,b.z,b.w};
    __nv_bfloat16 l[8];
    #pragma unroll
    for (int i = 0; i < 8; i++) {
        __nv_bfloat16 h = __float2bfloat16(v[i]);
        l[i] = __float2bfloat16(v[i] - __bfloat162float(h));
    }
    uint4 r;
    r.x = packb(l[0], l[1]); r.y = packb(l[2], l[3]);
    r.z = packb(l[4], l[5]); r.w = packb(l[6], l[7]);
    return r;
}

// ---------------- scratch (referenced ONLY from device code) ----------
__device__ float g_q[(size_t)NWIN*NH*BHD];
__device__ float g_k[(size_t)NWIN*NH*BHD];
__device__ float g_v[(size_t)NWIN*NH*BHD];
__device__ float g_bt[961*NH];
__device__ float g_rpbT[(size_t)NH*NTOK*NTOK];   // [h][j][qi]
__device__ __align__(16) __nv_bfloat16 g_qwh[1152*NC];
__device__ __align__(16) __nv_bfloat16 g_qwl[1152*NC];
__device__ __align__(16) __nv_bfloat16 g_pwh[NC*NC];
__device__ __align__(16) __nv_bfloat16 g_pwl[NC*NC];
__device__ __align__(16) __nv_bfloat16 g_aoh[(size_t)MROWS*NC];
__device__ __align__(16) __nv_bfloat16 g_aol[(size_t)MROWS*NC];

// ================= split fp32 -> bf16 hi + lo (weights only) ==============
__global__ void split_kernel(const float* __restrict__ src, int n4, int which)
{
    __nv_bfloat16* hi = (which == 0) ? g_qwh : g_pwh;
    __nv_bfloat16* lo = (which == 0) ? g_qwl : g_pwl;
    int i = blockIdx.x*blockDim.x + threadIdx.x;
    if (i >= n4) return;
    float4 v = ((const float4*)src)[i];
    float vals[4] = {v.x, v.y, v.z, v.w};
    __nv_bfloat16 h[4], l[4];
    #pragma unroll
    for (int j = 0; j < 4; j++) {
        h[j] = __float2bfloat16(vals[j]);
        l[j] = __float2bfloat16(vals[j] - __bfloat162float(h[j]));
    }
    ((__nv_bfloat162*)hi)[2*i+0] = __nv_bfloat162(h[0], h[1]);
    ((__nv_bfloat162*)hi)[2*i+1] = __nv_bfloat162(h[2], h[3]);
    ((__nv_bfloat162*)lo)[2*i+0] = __nv_bfloat162(l[0], l[1]);
    ((__nv_bfloat162*)lo)[2*i+1] = __nv_bfloat162(l[2], l[3]);
}

// ================= CPB MLP ==============
__global__ void cpb_kernel(const float* __restrict__ table,
                           const float* __restrict__ w1,
                           const float* __restrict__ b1,
                           const float* __restrict__ w2)
{
    __shared__ float sh[512];
    const int e = blockIdx.x;
    const int t = threadIdx.x;
    const float c0 = table[e*2+0], c1 = table[e*2+1];
    float hid = fmaf(c0, w1[t*2+0], fmaf(c1, w1[t*2+1], b1[t]));
    sh[t] = fmaxf(hid, 0.f);
    __syncthreads();
    const int w = t >> 5, l = t & 31;
    if (w < NH) {
        float s = 0.f;
        #pragma unroll
        for (int i = 0; i < 16; i++)
            s = fmaf(sh[l + i*32], w2[w*512 + l + i*32], s);
        #pragma unroll
        for (int o = 16; o > 0; o >>= 1)
            s += __shfl_xor_sync(0xffffffffu, s, o);
        if (l == 0) g_bt[e*NH + w] = s;
    }
}

__global__ void gather_kernel(const int* __restrict__ rpi)
{
    const int qi = threadIdx.x;
    const int j  = blockIdx.x;
    const int idx = rpi[qi*NTOK + j];
    #pragma unroll
    for (int h = 0; h < NH; h++) {
        float bv = g_bt[idx*NH + h];
        float sg = 16.f / (1.f + __expf(-bv));
        g_rpbT[((size_t)h*NTOK + j)*NTOK + qi] = sg;
    }
}

// ====================== shared GEMM compute step =========================
#define AS_STR 72
#define HM_STAGE (2*128*AS_STR)
#define HM_SMEM (2*HM_STAGE*2)

__device__ __forceinline__ void gemm_compute(
    u32 sA, u32 sB, int wm, int wn,
    int a_rr, int a_q, int b_no, int b_ko, float acc[4][4][4])
{
    #pragma unroll
    for (int ks = 0; ks < 4; ks++) {
        u32 a[4][4];
        #pragma unroll
        for (int mf = 0; mf < 4; mf++)
            ldmx4(a[mf], sA + ((wm*64 + mf*16 + a_rr)*AS_STR + ks*16 + a_q)*2);
        u32 b[4][2];
        #pragma unroll
        for (int nfp = 0; nfp < 2; nfp++) {
            u32 tmp[4];
            ldmx4(tmp, sB + ((wn*32 + nfp*16 + b_no)*AS_STR + ks*16 + b_ko)*2);
            b[2*nfp+0][0] = tmp[0]; b[2*nfp+0][1] = tmp[1];
            b[2*nfp+1][0] = tmp[2]; b[2*nfp+1][1] = tmp[3];
        }
        #pragma unroll
        for (int mf = 0; mf < 4; mf++)
            #pragma unroll
            for (int nf = 0; nf < 4; nf++)
                mma16816(acc[mf][nf], a[mf], b[nf][0], b[nf][1]);
    }
}

// ================= QKV GEMM: A = fp32 x, split inline ====================
__global__ __launch_bounds__(256, 2) void qkv_hm_kernel(
    const float* __restrict__ X,
    const float* __restrict__ qb, const float* __restrict__ vb)
{
    extern __shared__ __nv_bfloat16 smbf[];
    const int row0 = blockIdx.y * 128;
    const int col0 = blockIdx.x * 128;
    const int t = threadIdx.x;
    const int r = t >> 1, hf = t & 1;

    const float* aF = X + (size_t)(row0 + r)*NC + hf*32;
    const __nv_bfloat16* bH = g_qwh + (size_t)(col0 + r)*NC + hf*32;
    const __nv_bfloat16* bL = g_qwl + (size_t)(col0 + r)*NC + hf*32;

    uint4 ra[4], rb[4];
    auto gload = [&](int kt) {
        const int seg = kt / 6;
        const int kk  = (kt - seg*6) * 64;
        const float4* ap = (const float4*)(aF + kk);
        const uint4* bp = (const uint4*)(((seg == 1) ? bL : bH) + kk);
        if (seg == 2) {
            #pragma unroll
            for (int j = 0; j < 4; j++) ra[j] = pack8l(ap[2*j], ap[2*j+1]);
        } else {
            #pragma unroll
            for (int j = 0; j < 4; j++) ra[j] = pack8h(ap[2*j], ap[2*j+1]);
        }
        #pragma unroll
        for (int j = 0; j < 4; j++) rb[j] = bp[j];
    };
    auto stage_to = [&](int s) {
        __nv_bfloat16* as = smbf + s*HM_STAGE + r*AS_STR + hf*32;
        __nv_bfloat16* bs = as + 128*AS_STR;
        #pragma unroll
        for (int j = 0; j < 4; j++) {
            *(uint4*)(as + j*8) = ra[j];
            *(uint4*)(bs + j*8) = rb[j];
        }
    };

    const int wid = t >> 5, lane = t & 31;
    const int wm = wid & 1, wn = wid >> 1;
    const int a_rr = lane & 15;
    const int a_q  = (lane >> 4) << 3;
    const int b_no = ((lane >> 4) << 3) + (lane & 7);
    const int b_ko = ((lane >> 3) & 1) << 3;
    const u32 smem0 = smem_to_u32(smbf);

    float acc[4][4][4];
    #pragma unroll
    for (int i = 0; i < 4; i++)
        #pragma unroll
        for (int j = 0; j < 4; j++)
            #pragma unroll
            for (int k = 0; k < 4; k++) acc[i][j][k] = 0.f;

    gload(0);
    stage_to(0);
    gload(1);

    #pragma unroll 1
    for (int kt = 0; kt < 18; kt++) {
        __syncthreads();
        if (kt < 17) stage_to((kt + 1) & 1);
        if (kt + 2 < 18) gload(kt + 2);
        const u32 sA = smem0 + (u32)(kt & 1)*HM_STAGE*2;
        const u32 sB = sA + 128*AS_STR*2;
        gemm_compute(sA, sB, wm, wn, a_rr, a_q, b_no, b_ko, acc);
    }

    const int r_in = lane >> 2, c_in = (lane & 3)*2;
    #pragma unroll
    for (int nf = 0; nf < 4; nf++) {
        const int cg = col0 + wn*32 + nf*8 + c_in;
        const int which = cg / NC;
        const int cw = cg % NC;
        const int hh = cw >> 5, d0 = cw & 31;
        const float b0 = (which == 0) ? qb[cw]   : (which == 2) ? vb[cw]   : 0.f;
        const float b1 = (which == 0) ? qb[cw+1] : (which == 2) ? vb[cw+1] : 0.f;
        float* base = (which == 0) ? g_q : (which == 1) ? g_k : g_v;
        #pragma unroll
        for (int mf = 0; mf < 4; mf++) {
            int m0 = row0 + wm*64 + mf*16 + r_in;
            int bb = m0 >> 8, nn = m0 & 255;
            float* p = base + ((((size_t)bb*NH + hh)*NTOK) + nn)*DH + d0;
            *(float2*)p = make_float2(acc[mf][nf][0] + b0, acc[mf][nf][1] + b1);
            int m1 = m0 + 8; bb = m1 >> 8; nn = m1 & 255;
            p = base + ((((size_t)bb*NH + hh)*NTOK) + nn)*DH + d0;
            *(float2*)p = make_float2(acc[mf][nf][2] + b0, acc[mf][nf][3] + b1);
        }
    }
}

// ================= Proj GEMM (bf16 pre-split A, R13-proven) ==============
__global__ __launch_bounds__(256, 2) void proj_hm_kernel(
    const float* __restrict__ pb, float* __restrict__ out)
{
    extern __shared__ __nv_bfloat16 smbf[];
    const int row0 = blockIdx.y * 128;
    const int col0 = blockIdx.x * 128;
    const int t = threadIdx.x;
    const int r = t >> 1, hf = t & 1;

    const __nv_bfloat16* aH = g_aoh + (size_t)(row0 + r)*NC + hf*32;
    const __nv_bfloat16* aL = g_aol + (size_t)(row0 + r)*NC + hf*32;
    const __nv_bfloat16* bH = g_pwh + (size_t)(col0 + r)*NC + hf*32;
    const __nv_bfloat16* bL = g_pwl + (size_t)(col0 + r)*NC + hf*32;

    uint4 ra[4], rb[4];
    auto gload = [&](int kt) {
        const int seg = kt / 6;
        const int kk  = (kt - seg*6) * 64;
        const uint4* ap = (const uint4*)(((seg == 2) ? aL : aH) + kk);
        const uint4* bp = (const uint4*)(((seg == 1) ? bL : bH) + kk);
        #pragma unroll
        for (int j = 0; j < 4; j++) { ra[j] = ap[j]; rb[j] = bp[j]; }
    };
    auto stage_to = [&](int s) {
        __nv_bfloat16* as = smbf + s*HM_STAGE + r*AS_STR + hf*32;
        __nv_bfloat16* bs = as + 128*AS_STR;
        #pragma unroll
        for (int j = 0; j < 4; j++) {
            *(uint4*)(as + j*8) = ra[j];
            *(uint4*)(bs + j*8) = rb[j];
        }
    };

    const int wid = t >> 5, lane = t & 31;
    const int wm = wid & 1, wn = wid >> 1;
    const int a_rr = lane & 15;
    const int a_q  = (lane >> 4) << 3;
    const int b_no = ((lane >> 4) << 3) + (lane & 7);
    const int b_ko = ((lane >> 3) & 1) << 3;
    const u32 smem0 = smem_to_u32(smbf);

    float acc[4][4][4];
    #pragma unroll
    for (int i = 0; i < 4; i++)
        #pragma unroll
        for (int j = 0; j < 4; j++)
            #pragma unroll
            for (int k = 0; k < 4; k++) acc[i][j][k] = 0.f;

    gload(0);
    stage_to(0);
    gload(1);

    #pragma unroll 1
    for (int kt = 0; kt < 18; kt++) {
        __syncthreads();
        if (kt < 17) stage_to((kt + 1) & 1);
        if (kt + 2 < 18) gload(kt + 2);
        const u32 sA = smem0 + (u32)(kt & 1)*HM_STAGE*2;
        const u32 sB = sA + 128*AS_STR*2;
        gemm_compute(sA, sB, wm, wn, a_rr, a_q, b_no, b_ko, acc);
    }

    const int r_in = lane >> 2, c_in = (lane & 3)*2;
    #pragma unroll
    for (int nf = 0; nf < 4; nf++) {
        const int cg = col0 + wn*32 + nf*8 + c_in;
        const float b0 = pb[cg], b1 = pb[cg+1];
        #pragma unroll
        for (int mf = 0; mf < 4; mf++) {
            int m0 = row0 + wm*64 + mf*16 + r_in;
            *(float2*)(out + (size_t)m0*NC + cg) =
                make_float2(acc[mf][nf][0] + b0, acc[mf][nf][1] + b1);
            *(float2*)(out + (size_t)(m0+8)*NC + cg) =
                make_float2(acc[mf][nf][2] + b0, acc[mf][nf][3] + b1);
        }
    }
}

// ================= Attention (exact R13: HMMA bf16x3 + ldmatrix) =========
#define QSTR 40
#define VSTR 264
#define SQH 0
#define SQL 10240
#define SKH 20480
#define SKL 30720
#define SVH 40960
#define SVL 49408
#define ATT_SMEM ((49408 + 32*VSTR) * 2)   // 115712 B

__global__ __launch_bounds__(256) void attn_kernel(const float* __restrict__ logit_scale)
{
    extern __shared__ __nv_bfloat16 smb[];
    const int bh = blockIdx.x;
    const int h  = bh % NH;
    const int b  = bh / NH;
    const int t  = threadIdx.x;
    const int wid = t >> 5, lane = t & 31;
    const int gid = lane >> 2, tig = lane & 3;
    const int b_no = ((lane >> 4) << 3) + (lane & 7);
    const int b_ko = ((lane >> 3) & 1) << 3;

    const float sc = __expf(fminf(logit_scale[h], 4.6051702f));
    const float M  = sc + 16.f;

    {
        float v[DH]; float s;
        const float* p = g_k + (size_t)bh*BHD + t*DH;
        s = 0.f;
        #pragma unroll
        for (int d = 0; d < DH; d += 4) {
            float4 f = *(const float4*)(p + d);
            v[d]=f.x; v[d+1]=f.y; v[d+2]=f.z; v[d+3]=f.w;
        }
        #pragma unroll
        for (int d = 0; d < DH; d++) s = fmaf(v[d], v[d], s);
        float inv = 1.f / fmaxf(sqrtf(s), 1e-12f);
        #pragma unroll
        for (int i = 0; i < 16; i++) {
            __nv_bfloat16 h0,l0,h1,l1;
            splitb(v[2*i]*inv, h0, l0);
            splitb(v[2*i+1]*inv, h1, l1);
            *(u32*)&smb[SKH + t*QSTR + 2*i] = packb(h0, h1);
            *(u32*)&smb[SKL + t*QSTR + 2*i] = packb(l0, l1);
        }
        p = g_q + (size_t)bh*BHD + t*DH;
        s = 0.f;
        #pragma unroll
        for (int d = 0; d < DH; d += 4) {
            float4 f = *(const float4*)(p + d);
            v[d]=f.x; v[d+1]=f.y; v[d+2]=f.z; v[d+3]=f.w;
        }
        #pragma unroll
        for (int d = 0; d < DH; d++) s = fmaf(v[d], v[d], s);
        inv = sc / fmaxf(sqrtf(s), 1e-12f);
        #pragma unroll
        for (int i = 0; i < 16; i++) {
            __nv_bfloat16 h0,l0,h1,l1;
            splitb(v[2*i]*inv, h0, l0);
            splitb(v[2*i+1]*inv, h1, l1);
            *(u32*)&smb[SQH + t*QSTR + 2*i] = packb(h0, h1);
            *(u32*)&smb[SQL + t*QSTR + 2*i] = packb(l0, l1);
        }
        p = g_v + (size_t)bh*BHD + t*DH;
        #pragma unroll
        for (int d = 0; d < DH; d += 4) {
            float4 f = *(const float4*)(p + d);
            v[d]=f.x; v[d+1]=f.y; v[d+2]=f.z; v[d+3]=f.w;
        }
        #pragma unroll
        for (int d = 0; d < DH; d++) {
            __nv_bfloat16 h0,l0;
            splitb(v[d], h0, l0);
            smb[SVH + d*VSTR + t] = h0;
            smb[SVL + d*VSTR + t] = l0;
        }
    }
    __syncthreads();

    const u32 sKH = smem_to_u32(smb) + SKH*2;
    const u32 sKL = smem_to_u32(smb) + SKL*2;
    const u32 sVH = smem_to_u32(smb) + SVH*2;
    const u32 sVL = smem_to_u32(smb) + SVL*2;

    u32 qh[2][2][4], ql[2][2][4];
    #pragma unroll
    for (int mt = 0; mt < 2; mt++)
        #pragma unroll
        for (int ks = 0; ks < 2; ks++) {
            const int row = wid*32 + mt*16 + gid;
            const int k0  = ks*16 + 2*tig;
            qh[mt][ks][0] = *(const u32*)&smb[SQH + row*QSTR + k0];
            qh[mt][ks][1] = *(const u32*)&smb[SQH + (row+8)*QSTR + k0];
            qh[mt][ks][2] = *(const u32*)&smb[SQH + row*QSTR + k0 + 8];
            qh[mt][ks][3] = *(const u32*)&smb[SQH + (row+8)*QSTR + k0 + 8];
            ql[mt][ks][0] = *(const u32*)&smb[SQL + row*QSTR + k0];
            ql[mt][ks][1] = *(const u32*)&smb[SQL + (row+8)*QSTR + k0];
            ql[mt][ks][2] = *(const u32*)&smb[SQL + row*QSTR + k0 + 8];
            ql[mt][ks][3] = *(const u32*)&smb[SQL + (row+8)*QSTR + k0 + 8];
        }

    float acc[2][4][4];
    #pragma unroll
    for (int i = 0; i < 2; i++)
        #pragma unroll
        for (int j = 0; j < 4; j++)
            #pragma unroll
            for (int k = 0; k < 4; k++) acc[i][j][k] = 0.f;
    float lsum[4] = {0.f, 0.f, 0.f, 0.f};

    const float* rp = g_rpbT + (size_t)h*(NTOK*NTOK);

    #pragma unroll 1
    for (int kt = 0; kt < 16; kt++) {
        float rb[2][2][4];
        #pragma unroll
        for (int mt = 0; mt < 2; mt++)
            #pragma unroll
            for (int n8 = 0; n8 < 2; n8++) {
                const int col = kt*16 + n8*8 + 2*tig;
                const int row = wid*32 + mt*16 + gid;
                rb[mt][n8][0] = rp[col*NTOK + row];
                rb[mt][n8][1] = rp[(col+1)*NTOK + row];
                rb[mt][n8][2] = rp[col*NTOK + row + 8];
                rb[mt][n8][3] = rp[(col+1)*NTOK + row + 8];
            }

        u32 kbh[2][2][2], kbl[2][2][2];
        #pragma unroll
        for (int ks = 0; ks < 2; ks++) {
            u32 tmp[4];
            ldmx4(tmp, sKH + ((kt*16 + b_no)*QSTR + ks*16 + b_ko)*2);
            kbh[0][ks][0] = tmp[0]; kbh[0][ks][1] = tmp[1];
            kbh[1][ks][0] = tmp[2]; kbh[1][ks][1] = tmp[3];
            ldmx4(tmp, sKL + ((kt*16 + b_no)*QSTR + ks*16 + b_ko)*2);
            kbl[0][ks][0] = tmp[0]; kbl[0][ks][1] = tmp[1];
            kbl[1][ks][0] = tmp[2]; kbl[1][ks][1] = tmp[3];
        }

        float c[2][2][4];
        #pragma unroll
        for (int i = 0; i < 2; i++)
            #pragma unroll
            for (int j = 0; j < 2; j++)
                #pragma unroll
                for (int k = 0; k < 4; k++) c[i][j][k] = 0.f;
        #pragma unroll
        for (int mt = 0; mt < 2; mt++)
            #pragma unroll
            for (int n8 = 0; n8 < 2; n8++)
                #pragma unroll
                for (int ks = 0; ks < 2; ks++) {
                    mma16816(c[mt][n8], qh[mt][ks], kbh[n8][ks][0], kbh[n8][ks][1]);
                    mma16816(c[mt][n8], qh[mt][ks], kbl[n8][ks][0], kbl[n8][ks][1]);
                    mma16816(c[mt][n8], ql[mt][ks], kbh[n8][ks][0], kbh[n8][ks][1]);
                }

        #pragma unroll
        for (int mt = 0; mt < 2; mt++)
            #pragma unroll
            for (int n8 = 0; n8 < 2; n8++)
                #pragma unroll
                for (int e = 0; e < 4; e++) {
                    float pv = __expf(c[mt][n8][e] + rb[mt][n8][e] - M);
                    lsum[mt*2 + (e>>1)] += pv;
                    c[mt][n8][e] = pv;
                }

        u32 ah[2][4], al[2][4];
        #pragma unroll
        for (int mt = 0; mt < 2; mt++) {
            __nv_bfloat16 h0,l0,h1,l1;
            splitb(c[mt][0][0], h0, l0); splitb(c[mt][0][1], h1, l1);
            ah[mt][0] = packb(h0,h1); al[mt][0] = packb(l0,l1);
            splitb(c[mt][0][2], h0, l0); splitb(c[mt][0][3], h1, l1);
            ah[mt][1] = packb(h0,h1); al[mt][1] = packb(l0,l1);
            splitb(c[mt][1][0], h0, l0); splitb(c[mt][1][1], h1, l1);
            ah[mt][2] = packb(h0,h1); al[mt][2] = packb(l0,l1);
            splitb(c[mt][1][2], h0, l0); splitb(c[mt][1][3], h1, l1);
            ah[mt][3] = packb(h0,h1); al[mt][3] = packb(l0,l1);
        }

        u32 vh[4][2], vl[4][2];
        #pragma unroll
        for (int np = 0; np < 2; np++) {
            u32 tmp[4];
            ldmx4(tmp, sVH + ((np*16 + b_no)*VSTR + kt*16 + b_ko)*2);
            vh[2*np+0][0] = tmp[0]; vh[2*np+0][1] = tmp[1];
            vh[2*np+1][0] = tmp[2]; vh[2*np+1][1] = tmp[3];
            ldmx4(tmp, sVL + ((np*16 + b_no)*VSTR + kt*16 + b_ko)*2);
            vl[2*np+0][0] = tmp[0]; vl[2*np+0][1] = tmp[1];
            vl[2*np+1][0] = tmp[2]; vl[2*np+1][1] = tmp[3];
        }

        #pragma unroll
        for (int n8d = 0; n8d < 4; n8d++)
            #pragma unroll
            for (int mt = 0; mt < 2; mt++) {
                mma16816(acc[mt][n8d], ah[mt], vh[n8d][0], vh[n8d][1]);
                mma16816(acc[mt][n8d], ah[mt], vl[n8d][0], vl[n8d][1]);
                mma16816(acc[mt][n8d], al[mt], vh[n8d][0], vh[n8d][1]);
            }
    }

    #pragma unroll
    for (int i = 0; i < 4; i++) {
        lsum[i] += __shfl_xor_sync(0xffffffffu, lsum[i], 1);
        lsum[i] += __shfl_xor_sync(0xffffffffu, lsum[i], 2);
        lsum[i] = 1.f / lsum[i];
    }

    #pragma unroll
    for (int mt = 0; mt < 2; mt++)
        #pragma unroll
        for (int n8d = 0; n8d < 4; n8d++) {
            const int row0 = wid*32 + mt*16 + gid;
            const int dim  = n8d*8 + 2*tig;
            const float i0 = lsum[mt*2], i1 = lsum[mt*2+1];
            float v0 = acc[mt][n8d][0]*i0, v1 = acc[mt][n8d][1]*i0;
            float v2 = acc[mt][n8d][2]*i1, v3 = acc[mt][n8d][3]*i1;
            size_t o0 = ((size_t)(b*NTOK + row0))*NC + h*DH + dim;
            size_t o1 = ((size_t)(b*NTOK + row0 + 8))*NC + h*DH + dim;
            __nv_bfloat16 b0 = __float2bfloat16(v0), b1 = __float2bfloat16(v1);
            __nv_bfloat16 b2 = __float2bfloat16(v2), b3 = __float2bfloat16(v3);
            *(__nv_bfloat162*)&g_aoh[o0] = __nv_bfloat162(b0, b1);
            *(__nv_bfloat162*)&g_aoh[o1] = __nv_bfloat162(b2, b3);
            *(__nv_bfloat162*)&g_aol[o0] = __nv_bfloat162(
                __float2bfloat16(v0 - __bfloat162float(b0)),
                __float2bfloat16(v1 - __bfloat162float(b1)));
            *(__nv_bfloat162*)&g_aol[o1] = __nv_bfloat162(
                __float2bfloat16(v2 - __bfloat162float(b2)),
                __float2bfloat16(v3 - __bfloat162float(b3)));
        }
}

// =========================== launcher ====================================
extern "C" void kernel_launch(void* const* d_in, const int* in_sizes, int n_in,
                              void* d_out, int out_size)
{
    const float* x      = (const float*)d_in[0];
    const float* qkv_w  = (const float*)d_in[1];
    const float* q_bias = (const float*)d_in[2];
    const float* v_bias = (const float*)d_in[3];
    const float* lscale = (const float*)d_in[4];
    const float* cpb_w1 = (const float*)d_in[5];
    const float* cpb_b1 = (const float*)d_in[6];
    const float* cpb_w2 = (const float*)d_in[7];
    const float* proj_w = (const float*)d_in[8];
    const float* proj_b = (const float*)d_in[9];
    const float* rtab   = (const float*)d_in[10];
    const int*   rpi    = (const int*)d_in[11];
    float* out = (float*)d_out;

    cudaFuncSetAttribute(attn_kernel, cudaFuncAttributeMaxDynamicSharedMemorySize, ATT_SMEM);
    cudaFuncSetAttribute(qkv_hm_kernel, cudaFuncAttributeMaxDynamicSharedMemorySize, HM_SMEM);
    cudaFuncSetAttribute(proj_hm_kernel, cudaFuncAttributeMaxDynamicSharedMemorySize, HM_SMEM);

    // weight splits only (x split fused into qkv kernel)
    {
        int w4 = 1152*NC/4;
        split_kernel<<<(w4+255)/256, 256>>>(qkv_w, w4, 0);
        int p4 = NC*NC/4;
        split_kernel<<<(p4+255)/256, 256>>>(proj_w, p4, 1);
    }

    cpb_kernel<<<961, 512>>>(rtab, cpb_w1, cpb_b1, cpb_w2);
    gather_kernel<<<NTOK, NTOK>>>(rpi);

    dim3 gq(1152/128, MROWS/128);
    qkv_hm_kernel<<<gq, 256, HM_SMEM>>>(x, q_bias, v_bias);

    attn_kernel<<<NWIN*NH, 256, ATT_SMEM>>>(lscale);

    dim3 gp(NC/128, MROWS/128);
    proj_hm_kernel<<<gp, 256, HM_SMEM>>>(proj_b, out);
}

// round 16
// speedup vs baseline: 1.3379x; 1.3379x over previous
#include <cuda_runtime.h>
#include <cuda_bf16.h>
#include <math.h>

// ---------------- problem constants ----------------
#define NWIN 256
#define NTOK 256
#define NC   384
#define NH   12
#define DH   32
#define MROWS (NWIN*NTOK)
#define BHD (NTOK*DH)

typedef unsigned long long u64;
typedef unsigned int u32;

// ---------------- mma / ldmatrix helpers ------
__device__ __forceinline__ void mma16816(float c[4], const u32 a[4], u32 b0, u32 b1) {
    asm volatile(
        "mma.sync.aligned.m16n8k16.row.col.f32.bf16.bf16.f32 "
        "{%0,%1,%2,%3},{%4,%5,%6,%7},{%8,%9},{%0,%1,%2,%3};"
        : "+f"(c[0]), "+f"(c[1]), "+f"(c[2]), "+f"(c[3])
        : "r"(a[0]), "r"(a[1]), "r"(a[2]), "r"(a[3]), "r"(b0), "r"(b1));
}
__device__ __forceinline__ void ldmx4(u32 r[4], u32 addr) {
    asm volatile("ldmatrix.sync.aligned.m8n8.x4.shared.b16 {%0,%1,%2,%3}, [%4];"
        : "=r"(r[0]), "=r"(r[1]), "=r"(r[2]), "=r"(r[3]) : "r"(addr));
}
__device__ __forceinline__ u32 smem_to_u32(const void* p) {
    u32 a;
    asm("{ .reg .u64 t; cvta.to.shared.u64 t, %1; cvt.u32.u64 %0, t; }" : "=r"(a) : "l"(p));
    return a;
}
__device__ __forceinline__ void splitb(float x, __nv_bfloat16& hh, __nv_bfloat16& hl) {
    hh = __float2bfloat16(x);
    hl = __float2bfloat16(x - __bfloat162float(hh));
}
__device__ __forceinline__ u32 packb(__nv_bfloat16 a, __nv_bfloat16 b) {
    __nv_bfloat162 h(a, b);
    return *(u32*)&h;
}

// ---------------- scratch (referenced ONLY from device code) ----------
__device__ float g_q[(size_t)NWIN*NH*BHD];
__device__ float g_k[(size_t)NWIN*NH*BHD];
__device__ float g_v[(size_t)NWIN*NH*BHD];
__device__ float g_bt[961*NH];
__device__ float g_rpbT[(size_t)NH*NTOK*NTOK];   // [h][j][qi]
__device__ __align__(16) __nv_bfloat16 g_xh[(size_t)MROWS*NC];
__device__ __align__(16) __nv_bfloat16 g_xl[(size_t)MROWS*NC];
__device__ __align__(16) __nv_bfloat16 g_qwh[1152*NC];
__device__ __align__(16) __nv_bfloat16 g_qwl[1152*NC];
__device__ __align__(16) __nv_bfloat16 g_pwh[NC*NC];
__device__ __align__(16) __nv_bfloat16 g_pwl[NC*NC];
__device__ __align__(16) __nv_bfloat16 g_aoh[(size_t)MROWS*NC];
__device__ __align__(16) __nv_bfloat16 g_aol[(size_t)MROWS*NC];

// ========== split fp32 -> bf16 hi + lo (x + both weights, one launch) ====
#define XN4 (MROWS*NC/4)
#define WN4 (1152*NC/4)
#define PN4 (NC*NC/4)
__global__ void split_kernel(const float* __restrict__ x,
                             const float* __restrict__ qw,
                             const float* __restrict__ pw)
{
    int i = blockIdx.x*blockDim.x + threadIdx.x;
    const float* src;
    __nv_bfloat16 *hi, *lo;
    if (i < XN4)            { src = x;  hi = g_xh;  lo = g_xl;  }
    else if (i < XN4+WN4)   { i -= XN4; src = qw; hi = g_qwh; lo = g_qwl; }
    else if (i < XN4+WN4+PN4){ i -= XN4+WN4; src = pw; hi = g_pwh; lo = g_pwl; }
    else return;
    float4 v = ((const float4*)src)[i];
    float vals[4] = {v.x, v.y, v.z, v.w};
    __nv_bfloat16 h[4], l[4];
    #pragma unroll
    for (int j = 0; j < 4; j++) {
        h[j] = __float2bfloat16(vals[j]);
        l[j] = __float2bfloat16(vals[j] - __bfloat162float(h[j]));
    }
    ((__nv_bfloat162*)hi)[2*i+0] = __nv_bfloat162(h[0], h[1]);
    ((__nv_bfloat162*)hi)[2*i+1] = __nv_bfloat162(h[2], h[3]);
    ((__nv_bfloat162*)lo)[2*i+0] = __nv_bfloat162(l[0], l[1]);
    ((__nv_bfloat162*)lo)[2*i+1] = __nv_bfloat162(l[2], l[3]);
}

// ================= CPB MLP ==============
__global__ void cpb_kernel(const float* __restrict__ table,
                           const float* __restrict__ w1,
                           const float* __restrict__ b1,
                           const float* __restrict__ w2)
{
    __shared__ float sh[512];
    const int e = blockIdx.x;
    const int t = threadIdx.x;
    const float c0 = table[e*2+0], c1 = table[e*2+1];
    float hid = fmaf(c0, w1[t*2+0], fmaf(c1, w1[t*2+1], b1[t]));
    sh[t] = fmaxf(hid, 0.f);
    __syncthreads();
    const int w = t >> 5, l = t & 31;
    if (w < NH) {
        float s = 0.f;
        #pragma unroll
        for (int i = 0; i < 16; i++)
            s = fmaf(sh[l + i*32], w2[w*512 + l + i*32], s);
        #pragma unroll
        for (int o = 16; o > 0; o >>= 1)
            s += __shfl_xor_sync(0xffffffffu, s, o);
        if (l == 0) g_bt[e*NH + w] = s;
    }
}

__global__ void gather_kernel(const int* __restrict__ rpi)
{
    const int qi = threadIdx.x;
    const int j  = blockIdx.x;
    const int idx = rpi[qi*NTOK + j];
    #pragma unroll
    for (int h = 0; h < NH; h++) {
        float bv = g_bt[idx*NH + h];
        float sg = 16.f / (1.f + __expf(-bv));
        g_rpbT[((size_t)h*NTOK + j)*NTOK + qi] = sg;
    }
}

// ====================== HMMA bf16x3 GEMM (R13-proven) ====
#define AS_STR 72
#define HM_STAGE (2*128*AS_STR)
#define HM_SMEM (2*HM_STAGE*2)

__device__ __forceinline__ void hmma_mainloop(
    const __nv_bfloat16* __restrict__ Ah, const __nv_bfloat16* __restrict__ Al,
    const __nv_bfloat16* __restrict__ Bh, const __nv_bfloat16* __restrict__ Bl,
    int row0, int col0, __nv_bfloat16* smbf, float acc[4][4][4])
{
    const int t = threadIdx.x;
    const int r = t >> 1, hf = t & 1;

    const __nv_bfloat16* aH = Ah + (size_t)(row0 + r)*NC + hf*32;
    const __nv_bfloat16* aL = Al + (size_t)(row0 + r)*NC + hf*32;
    const __nv_bfloat16* bH = Bh + (size_t)(col0 + r)*NC + hf*32;
    const __nv_bfloat16* bL = Bl + (size_t)(col0 + r)*NC + hf*32;

    uint4 ra[4], rb[4];
    auto gload = [&](int kt) {
        const int seg = kt / 6;
        const int kk  = (kt - seg*6) * 64;
        const uint4* ap = (const uint4*)(((seg == 2) ? aL : aH) + kk);
        const uint4* bp = (const uint4*)(((seg == 1) ? bL : bH) + kk);
        #pragma unroll
        for (int j = 0; j < 4; j++) { ra[j] = ap[j]; rb[j] = bp[j]; }
    };
    auto stage_to = [&](int s) {
        __nv_bfloat16* as = smbf + s*HM_STAGE + r*AS_STR + hf*32;
        __nv_bfloat16* bs = as + 128*AS_STR;
        #pragma unroll
        for (int j = 0; j < 4; j++) {
            *(uint4*)(as + j*8) = ra[j];
            *(uint4*)(bs + j*8) = rb[j];
        }
    };

    const int wid = t >> 5, lane = t & 31;
    const int wm = wid & 1, wn = wid >> 1;
    const int a_rr = lane & 15;
    const int a_q  = (lane >> 4) << 3;
    const int b_no = ((lane >> 4) << 3) + (lane & 7);
    const int b_ko = ((lane >> 3) & 1) << 3;
    const u32 smem0 = smem_to_u32(smbf);

    gload(0);
    stage_to(0);
    gload(1);

    #pragma unroll 1
    for (int kt = 0; kt < 18; kt++) {
        __syncthreads();
        if (kt < 17) stage_to((kt + 1) & 1);
        if (kt + 2 < 18) gload(kt + 2);

        const u32 sA = smem0 + (u32)(kt & 1)*HM_STAGE*2;
        const u32 sB = sA + 128*AS_STR*2;

        #pragma unroll
        for (int ks = 0; ks < 4; ks++) {
            u32 a[4][4];
            #pragma unroll
            for (int mf = 0; mf < 4; mf++)
                ldmx4(a[mf], sA + ((wm*64 + mf*16 + a_rr)*AS_STR + ks*16 + a_q)*2);
            u32 b[4][2];
            #pragma unroll
            for (int nfp = 0; nfp < 2; nfp++) {
                u32 tmp[4];
                ldmx4(tmp, sB + ((wn*32 + nfp*16 + b_no)*AS_STR + ks*16 + b_ko)*2);
                b[2*nfp+0][0] = tmp[0]; b[2*nfp+0][1] = tmp[1];
                b[2*nfp+1][0] = tmp[2]; b[2*nfp+1][1] = tmp[3];
            }
            #pragma unroll
            for (int mf = 0; mf < 4; mf++)
                #pragma unroll
                for (int nf = 0; nf < 4; nf++)
                    mma16816(acc[mf][nf], a[mf], b[nf][0], b[nf][1]);
        }
    }
}

// ================= QKV GEMM (HMMA) ===========
__global__ __launch_bounds__(256, 2) void qkv_hm_kernel(
    const float* __restrict__ qb, const float* __restrict__ vb)
{
    extern __shared__ __nv_bfloat16 smbf[];
    const int row0 = blockIdx.y * 128;
    const int col0 = blockIdx.x * 128;

    float acc[4][4][4];
    #pragma unroll
    for (int i = 0; i < 4; i++)
        #pragma unroll
        for (int j = 0; j < 4; j++)
            #pragma unroll
            for (int k = 0; k < 4; k++) acc[i][j][k] = 0.f;

    hmma_mainloop(g_xh, g_xl, g_qwh, g_qwl, row0, col0, smbf, acc);

    const int t = threadIdx.x;
    const int wid = t >> 5, lane = t & 31;
    const int wm = wid & 1, wn = wid >> 1;
    const int r_in = lane >> 2, c_in = (lane & 3)*2;

    #pragma unroll
    for (int nf = 0; nf < 4; nf++) {
        const int cg = col0 + wn*32 + nf*8 + c_in;
        const int which = cg / NC;
        const int cw = cg % NC;
        const int hh = cw >> 5, d0 = cw & 31;
        const float b0 = (which == 0) ? qb[cw]   : (which == 2) ? vb[cw]   : 0.f;
        const float b1 = (which == 0) ? qb[cw+1] : (which == 2) ? vb[cw+1] : 0.f;
        float* base = (which == 0) ? g_q : (which == 1) ? g_k : g_v;
        #pragma unroll
        for (int mf = 0; mf < 4; mf++) {
            int m0 = row0 + wm*64 + mf*16 + r_in;
            int bb = m0 >> 8, nn = m0 & 255;
            float* p = base + ((((size_t)bb*NH + hh)*NTOK) + nn)*DH + d0;
            *(float2*)p = make_float2(acc[mf][nf][0] + b0, acc[mf][nf][1] + b1);
            int m1 = m0 + 8; bb = m1 >> 8; nn = m1 & 255;
            p = base + ((((size_t)bb*NH + hh)*NTOK) + nn)*DH + d0;
            *(float2*)p = make_float2(acc[mf][nf][2] + b0, acc[mf][nf][3] + b1);
        }
    }
}

// ================= Proj GEMM (HMMA) ===========
__global__ __launch_bounds__(256, 2) void proj_hm_kernel(
    const float* __restrict__ pb, float* __restrict__ out)
{
    extern __shared__ __nv_bfloat16 smbf[];
    const int row0 = blockIdx.y * 128;
    const int col0 = blockIdx.x * 128;

    float acc[4][4][4];
    #pragma unroll
    for (int i = 0; i < 4; i++)
        #pragma unroll
        for (int j = 0; j < 4; j++)
            #pragma unroll
            for (int k = 0; k < 4; k++) acc[i][j][k] = 0.f;

    hmma_mainloop(g_aoh, g_aol, g_pwh, g_pwl, row0, col0, smbf, acc);

    const int t = threadIdx.x;
    const int wid = t >> 5, lane = t & 31;
    const int wm = wid & 1, wn = wid >> 1;
    const int r_in = lane >> 2, c_in = (lane & 3)*2;

    #pragma unroll
    for (int nf = 0; nf < 4; nf++) {
        const int cg = col0 + wn*32 + nf*8 + c_in;
        const float b0 = pb[cg], b1 = pb[cg+1];
        #pragma unroll
        for (int mf = 0; mf < 4; mf++) {
            int m0 = row0 + wm*64 + mf*16 + r_in;
            *(float2*)(out + (size_t)m0*NC + cg) =
                make_float2(acc[mf][nf][0] + b0, acc[mf][nf][1] + b1);
            *(float2*)(out + (size_t)(m0+8)*NC + cg) =
                make_float2(acc[mf][nf][2] + b0, acc[mf][nf][3] + b1);
        }
    }
}

// ================= Attention (exact R13: HMMA bf16x3 + ldmatrix) =========
#define QSTR 40
#define VSTR 264
#define SQH 0
#define SQL 10240
#define SKH 20480
#define SKL 30720
#define SVH 40960
#define SVL 49408
#define ATT_SMEM ((49408 + 32*VSTR) * 2)   // 115712 B

__global__ __launch_bounds__(256) void attn_kernel(const float* __restrict__ logit_scale)
{
    extern __shared__ __nv_bfloat16 smb[];
    const int bh = blockIdx.x;
    const int h  = bh % NH;
    const int b  = bh / NH;
    const int t  = threadIdx.x;
    const int wid = t >> 5, lane = t & 31;
    const int gid = lane >> 2, tig = lane & 3;
    const int b_no = ((lane >> 4) << 3) + (lane & 7);
    const int b_ko = ((lane >> 3) & 1) << 3;

    const float sc = __expf(fminf(logit_scale[h], 4.6051702f));
    const float M  = sc + 16.f;

    {
        float v[DH]; float s;
        const float* p = g_k + (size_t)bh*BHD + t*DH;
        s = 0.f;
        #pragma unroll
        for (int d = 0; d < DH; d += 4) {
            float4 f = *(const float4*)(p + d);
            v[d]=f.x; v[d+1]=f.y; v[d+2]=f.z; v[d+3]=f.w;
        }
        #pragma unroll
        for (int d = 0; d < DH; d++) s = fmaf(v[d], v[d], s);
        float inv = 1.f / fmaxf(sqrtf(s), 1e-12f);
        #pragma unroll
        for (int i = 0; i < 16; i++) {
            __nv_bfloat16 h0,l0,h1,l1;
            splitb(v[2*i]*inv, h0, l0);
            splitb(v[2*i+1]*inv, h1, l1);
            *(u32*)&smb[SKH + t*QSTR + 2*i] = packb(h0, h1);
            *(u32*)&smb[SKL + t*QSTR + 2*i] = packb(l0, l1);
        }
        p = g_q + (size_t)bh*BHD + t*DH;
        s = 0.f;
        #pragma unroll
        for (int d = 0; d < DH; d += 4) {
            float4 f = *(const float4*)(p + d);
            v[d]=f.x; v[d+1]=f.y; v[d+2]=f.z; v[d+3]=f.w;
        }
        #pragma unroll
        for (int d = 0; d < DH; d++) s = fmaf(v[d], v[d], s);
        inv = sc / fmaxf(sqrtf(s), 1e-12f);
        #pragma unroll
        for (int i = 0; i < 16; i++) {
            __nv_bfloat16 h0,l0,h1,l1;
            splitb(v[2*i]*inv, h0, l0);
            splitb(v[2*i+1]*inv, h1, l1);
            *(u32*)&smb[SQH + t*QSTR + 2*i] = packb(h0, h1);
            *(u32*)&smb[SQL + t*QSTR + 2*i] = packb(l0, l1);
        }
        p = g_v + (size_t)bh*BHD + t*DH;
        #pragma unroll
        for (int d = 0; d < DH; d += 4) {
            float4 f = *(const float4*)(p + d);
            v[d]=f.x; v[d+1]=f.y; v[d+2]=f.z; v[d+3]=f.w;
        }
        #pragma unroll
        for (int d = 0; d < DH; d++) {
            __nv_bfloat16 h0,l0;
            splitb(v[d], h0, l0);
            smb[SVH + d*VSTR + t] = h0;
            smb[SVL + d*VSTR + t] = l0;
        }
    }
    __syncthreads();

    const u32 sKH = smem_to_u32(smb) + SKH*2;
    const u32 sKL = smem_to_u32(smb) + SKL*2;
    const u32 sVH = smem_to_u32(smb) + SVH*2;
    const u32 sVL = smem_to_u32(smb) + SVL*2;

    u32 qh[2][2][4], ql[2][2][4];
    #pragma unroll
    for (int mt = 0; mt < 2; mt++)
        #pragma unroll
        for (int ks = 0; ks < 2; ks++) {
            const int row = wid*32 + mt*16 + gid;
            const int k0  = ks*16 + 2*tig;
            qh[mt][ks][0] = *(const u32*)&smb[SQH + row*QSTR + k0];
            qh[mt][ks][1] = *(const u32*)&smb[SQH + (row+8)*QSTR + k0];
            qh[mt][ks][2] = *(const u32*)&smb[SQH + row*QSTR + k0 + 8];
            qh[mt][ks][3] = *(const u32*)&smb[SQH + (row+8)*QSTR + k0 + 8];
            ql[mt][ks][0] = *(const u32*)&smb[SQL + row*QSTR + k0];
            ql[mt][ks][1] = *(const u32*)&smb[SQL + (row+8)*QSTR + k0];
            ql[mt][ks][2] = *(const u32*)&smb[SQL + row*QSTR + k0 + 8];
            ql[mt][ks][3] = *(const u32*)&smb[SQL + (row+8)*QSTR + k0 + 8];
        }

    float acc[2][4][4];
    #pragma unroll
    for (int i = 0; i < 2; i++)
        #pragma unroll
        for (int j = 0; j < 4; j++)
            #pragma unroll
            for (int k = 0; k < 4; k++) acc[i][j][k] = 0.f;
    float lsum[4] = {0.f, 0.f, 0.f, 0.f};

    const float* rp = g_rpbT + (size_t)h*(NTOK*NTOK);

    #pragma unroll 1
    for (int kt = 0; kt < 16; kt++) {
        float rb[2][2][4];
        #pragma unroll
        for (int mt = 0; mt < 2; mt++)
            #pragma unroll
            for (int n8 = 0; n8 < 2; n8++) {
                const int col = kt*16 + n8*8 + 2*tig;
                const int row = wid*32 + mt*16 + gid;
                rb[mt][n8][0] = rp[col*NTOK + row];
                rb[mt][n8][1] = rp[(col+1)*NTOK + row];
                rb[mt][n8][2] = rp[col*NTOK + row + 8];
                rb[mt][n8][3] = rp[(col+1)*NTOK + row + 8];
            }

        u32 kbh[2][2][2], kbl[2][2][2];
        #pragma unroll
        for (int ks = 0; ks < 2; ks++) {
            u32 tmp[4];
            ldmx4(tmp, sKH + ((kt*16 + b_no)*QSTR + ks*16 + b_ko)*2);
            kbh[0][ks][0] = tmp[0]; kbh[0][ks][1] = tmp[1];
            kbh[1][ks][0] = tmp[2]; kbh[1][ks][1] = tmp[3];
            ldmx4(tmp, sKL + ((kt*16 + b_no)*QSTR + ks*16 + b_ko)*2);
            kbl[0][ks][0] = tmp[0]; kbl[0][ks][1] = tmp[1];
            kbl[1][ks][0] = tmp[2]; kbl[1][ks][1] = tmp[3];
        }

        float c[2][2][4];
        #pragma unroll
        for (int i = 0; i < 2; i++)
            #pragma unroll
            for (int j = 0; j < 2; j++)
                #pragma unroll
                for (int k = 0; k < 4; k++) c[i][j][k] = 0.f;
        #pragma unroll
        for (int mt = 0; mt < 2; mt++)
            #pragma unroll
            for (int n8 = 0; n8 < 2; n8++)
                #pragma unroll
                for (int ks = 0; ks < 2; ks++) {
                    mma16816(c[mt][n8], qh[mt][ks], kbh[n8][ks][0], kbh[n8][ks][1]);
                    mma16816(c[mt][n8], qh[mt][ks], kbl[n8][ks][0], kbl[n8][ks][1]);
                    mma16816(c[mt][n8], ql[mt][ks], kbh[n8][ks][0], kbh[n8][ks][1]);
                }

        #pragma unroll
        for (int mt = 0; mt < 2; mt++)
            #pragma unroll
            for (int n8 = 0; n8 < 2; n8++)
                #pragma unroll
                for (int e = 0; e < 4; e++) {
                    float pv = __expf(c[mt][n8][e] + rb[mt][n8][e] - M);
                    lsum[mt*2 + (e>>1)] += pv;
                    c[mt][n8][e] = pv;
                }

        u32 ah[2][4], al[2][4];
        #pragma unroll
        for (int mt = 0; mt < 2; mt++) {
            __nv_bfloat16 h0,l0,h1,l1;
            splitb(c[mt][0][0], h0, l0); splitb(c[mt][0][1], h1, l1);
            ah[mt][0] = packb(h0,h1); al[mt][0] = packb(l0,l1);
            splitb(c[mt][0][2], h0, l0); splitb(c[mt][0][3], h1, l1);
            ah[mt][1] = packb(h0,h1); al[mt][1] = packb(l0,l1);
            splitb(c[mt][1][0], h0, l0); splitb(c[mt][1][1], h1, l1);
            ah[mt][2] = packb(h0,h1); al[mt][2] = packb(l0,l1);
            splitb(c[mt][1][2], h0, l0); splitb(c[mt][1][3], h1, l1);
            ah[mt][3] = packb(h0,h1); al[mt][3] = packb(l0,l1);
        }

        u32 vh[4][2], vl[4][2];
        #pragma unroll
        for (int np = 0; np < 2; np++) {
            u32 tmp[4];
            ldmx4(tmp, sVH + ((np*16 + b_no)*VSTR + kt*16 + b_ko)*2);
            vh[2*np+0][0] = tmp[0]; vh[2*np+0][1] = tmp[1];
            vh[2*np+1][0] = tmp[2]; vh[2*np+1][1] = tmp[3];
            ldmx4(tmp, sVL + ((np*16 + b_no)*VSTR + kt*16 + b_ko)*2);
            vl[2*np+0][0] = tmp[0]; vl[2*np+0][1] = tmp[1];
            vl[2*np+1][0] = tmp[2]; vl[2*np+1][1] = tmp[3];
        }

        #pragma unroll
        for (int n8d = 0; n8d < 4; n8d++)
            #pragma unroll
            for (int mt = 0; mt < 2; mt++) {
                mma16816(acc[mt][n8d], ah[mt], vh[n8d][0], vh[n8d][1]);
                mma16816(acc[mt][n8d], ah[mt], vl[n8d][0], vl[n8d][1]);
                mma16816(acc[mt][n8d], al[mt], vh[n8d][0], vh[n8d][1]);
            }
    }

    #pragma unroll
    for (int i = 0; i < 4; i++) {
        lsum[i] += __shfl_xor_sync(0xffffffffu, lsum[i], 1);
        lsum[i] += __shfl_xor_sync(0xffffffffu, lsum[i], 2);
        lsum[i] = 1.f / lsum[i];
    }

    #pragma unroll
    for (int mt = 0; mt < 2; mt++)
        #pragma unroll
        for (int n8d = 0; n8d < 4; n8d++) {
            const int row0 = wid*32 + mt*16 + gid;
            const int dim  = n8d*8 + 2*tig;
            const float i0 = lsum[mt*2], i1 = lsum[mt*2+1];
            float v0 = acc[mt][n8d][0]*i0, v1 = acc[mt][n8d][1]*i0;
            float v2 = acc[mt][n8d][2]*i1, v3 = acc[mt][n8d][3]*i1;
            size_t o0 = ((size_t)(b*NTOK + row0))*NC + h*DH + dim;
            size_t o1 = ((size_t)(b*NTOK + row0 + 8))*NC + h*DH + dim;
            __nv_bfloat16 b0 = __float2bfloat16(v0), b1 = __float2bfloat16(v1);
            __nv_bfloat16 b2 = __float2bfloat16(v2), b3 = __float2bfloat16(v3);
            *(__nv_bfloat162*)&g_aoh[o0] = __nv_bfloat162(b0, b1);
            *(__nv_bfloat162*)&g_aoh[o1] = __nv_bfloat162(b2, b3);
            *(__nv_bfloat162*)&g_aol[o0] = __nv_bfloat162(
                __float2bfloat16(v0 - __bfloat162float(b0)),
                __float2bfloat16(v1 - __bfloat162float(b1)));
            *(__nv_bfloat162*)&g_aol[o1] = __nv_bfloat162(
                __float2bfloat16(v2 - __bfloat162float(b2)),
                __float2bfloat16(v3 - __bfloat162float(b3)));
        }
}

// =========================== launcher ====================================
extern "C" void kernel_launch(void* const* d_in, const int* in_sizes, int n_in,
                              void* d_out, int out_size)
{
    const float* x      = (const float*)d_in[0];
    const float* qkv_w  = (const float*)d_in[1];
    const float* q_bias = (const float*)d_in[2];
    const float* v_bias = (const float*)d_in[3];
    const float* lscale = (const float*)d_in[4];
    const float* cpb_w1 = (const float*)d_in[5];
    const float* cpb_b1 = (const float*)d_in[6];
    const float* cpb_w2 = (const float*)d_in[7];
    const float* proj_w = (const float*)d_in[8];
    const float* proj_b = (const float*)d_in[9];
    const float* rtab   = (const float*)d_in[10];
    const int*   rpi    = (const int*)d_in[11];
    float* out = (float*)d_out;

    cudaFuncSetAttribute(attn_kernel, cudaFuncAttributeMaxDynamicSharedMemorySize, ATT_SMEM);
    cudaFuncSetAttribute(qkv_hm_kernel, cudaFuncAttributeMaxDynamicSharedMemorySize, HM_SMEM);
    cudaFuncSetAttribute(proj_hm_kernel, cudaFuncAttributeMaxDynamicSharedMemorySize, HM_SMEM);

    // one launch splits x + both weights
    {
        int total = XN4 + WN4 + PN4;
        split_kernel<<<(total+255)/256, 256>>>(x, qkv_w, proj_w);
    }

    cpb_kernel<<<961, 512>>>(rtab, cpb_w1, cpb_b1, cpb_w2);
    gather_kernel<<<NTOK, NTOK>>>(rpi);

    dim3 gq(1152/128, MROWS/128);
    qkv_hm_kernel<<<gq, 256, HM_SMEM>>>(q_bias, v_bias);

    attn_kernel<<<NWIN*NH, 256, ATT_SMEM>>>(lscale);

    dim3 gp(NC/128, MROWS/128);
    proj_hm_kernel<<<gp, 256, HM_SMEM>>>(proj_b, out);
}